// round 2
// baseline (speedup 1.0000x reference)
#include <cuda_runtime.h>
#include <cuda_bf16.h>
#include <math.h>

#define NPTS 4096
#define BATCH 8
#define NROWS (BATCH*NPTS)     // 32768
#define DK 100
#define KNB 20
#define TPB 128

// ---------------- device scratch (no runtime allocation allowed) ----------------
__device__ double g_msum[64];
__device__ double g_msumsq[64];
__device__ double g_M1[6];
__device__ double g_M2[21];
__device__ double g_hsum[512];          // [b][o]
__device__ float  g_mpre[NROWS * 64];   // [row][o]
__device__ int    g_idx[NROWS * DK];    // [row][100]
__device__ int    g_selidx[NROWS * KNB];// [row][20]
__device__ float  g_rm[64], g_meanm[64];   // m-BN rsqrt / mean
__device__ float  g_r1[64], g_mean1[64];   // h-BN rsqrt / mean
__device__ float  g_s2[512];            // SE gate [b][o]

// ---------------- K0: zero accumulators ----------------
__global__ void k0_zero() {
    int t = threadIdx.x;
    if (t < 64) { g_msum[t] = 0.0; g_msumsq[t] = 0.0; }
    if (t < 6)  g_M1[t] = 0.0;
    if (t < 21) g_M2[t] = 0.0;
    if (t < 512) g_hsum[t] = 0.0;
}

// ---------------- K1: per-row top-100 select + sort + W_op1 matmul ----------------
__device__ __forceinline__ int scan_find(unsigned* hist, int H, int rankv,
                                         int tid, int lane, int wid,
                                         unsigned* warpS, int* bc) {
    int chunk = H >> 7;          // H / 128
    int base = tid * chunk;
    unsigned local = 0;
    for (int i = 0; i < chunk; ++i) local += hist[base + i];
    unsigned v = local;
    #pragma unroll
    for (int off = 1; off < 32; off <<= 1) {
        unsigned t2 = __shfl_up_sync(0xFFFFFFFFu, v, off);
        if (lane >= off) v += t2;
    }
    if (lane == 31) warpS[wid] = v;
    __syncthreads();
    if (tid == 0) {
        unsigned s = 0;
        for (int w = 0; w < 4; ++w) { unsigned t2 = warpS[w]; warpS[w] = s; s += t2; }
    }
    __syncthreads();
    unsigned incl = v + warpS[wid];
    unsigned excl = incl - local;
    if (excl < (unsigned)rankv && (unsigned)rankv <= incl) {
        unsigned c = excl;
        for (int i = 0; i < chunk; ++i) {
            unsigned h = hist[base + i];
            if (c < (unsigned)rankv && (unsigned)rankv <= c + h) { bc[0] = base + i; bc[1] = (int)c; break; }
            c += h;
        }
    }
    __syncthreads();
    return bc[0];
}

__global__ __launch_bounds__(TPB) void k1_topk(const float* __restrict__ x,
                                               const float* __restrict__ W_op1) {
    extern __shared__ char smem_raw[];
    unsigned long long* cand = (unsigned long long*)smem_raw;            // 128 * 8 = 1024
    float*    xs     = (float*)(smem_raw + 1024);                        // 3*4096*4 = 49152
    unsigned* keys   = (unsigned*)(smem_raw + 50176);                    // 4096*4 = 16384
    unsigned* hist   = (unsigned*)(smem_raw + 66560);                    // 2048*4 = 8192
    unsigned* eqbuf  = (unsigned*)(smem_raw + 74752);                    // 128*4 = 512
    float*    metric_s = (float*)(smem_raw + 75264);                     // 128*4 = 512
    unsigned* warpS  = (unsigned*)(smem_raw + 75776);                    // 16
    int*      bc     = (int*)(smem_raw + 75792);                         // 8
    int*      cnt    = (int*)(smem_raw + 75800);                         // 8
    float*    xsq    = (float*)(smem_raw + 75808);                       // 4096*4 = 16384 -> 92192 total

    int tid = threadIdx.x, lane = tid & 31, wid = tid >> 5;
    int b = blockIdx.y;
    const float* xb = x + b * 3 * NPTS;
    for (int i = tid; i < 3 * NPTS; i += TPB) xs[i] = xb[i];
    __syncthreads();
    // xx[j] = (x0*x0 + x1*x1) + x2*x2 with separate roundings (match XLA mul+reduce, no fma)
    for (int j = tid; j < NPTS; j += TPB) {
        float a0 = xs[j], a1 = xs[NPTS + j], a2 = xs[2 * NPTS + j];
        xsq[j] = __fadd_rn(__fadd_rn(__fmul_rn(a0, a0), __fmul_rn(a1, a1)), __fmul_rn(a2, a2));
    }
    __syncthreads();

    double msum = 0.0, msq = 0.0;

    for (int r = 0; r < 64; ++r) {
        int n = blockIdx.x * 64 + r;
        float x0n = xs[n], x1n = xs[NPTS + n], x2n = xs[2 * NPTS + n];
        float xxn = xsq[n];
        for (int j = tid; j < NPTS; j += TPB) {
            float a0 = xs[j], a1 = xs[NPTS + j], a2 = xs[2 * NPTS + j];
            // inner: cublas-style ascending-k fma chain
            float inner = __fmul_rn(x0n, a0);
            inner = fmaf(x1n, a1, inner);
            inner = fmaf(x2n, a2, inner);
            // pairwise = (2*inner - xx_n) - xx_m, no fma contraction (2*inner exact)
            float t2v = __fsub_rn(__fmul_rn(2.0f, inner), xxn);
            float p   = __fsub_rn(t2v, xsq[j]);
            unsigned bits = __float_as_uint(p);
            unsigned u = (bits & 0x80000000u) ? ~bits : (bits | 0x80000000u);
            keys[j] = ~u;   // ascending key == descending p
        }
        int rank = DK;
        // ---- level 1: bits [31:21] ----
        for (int i = tid; i < 2048; i += TPB) hist[i] = 0;
        __syncthreads();
        for (int j = tid; j < NPTS; j += TPB) atomicAdd(&hist[keys[j] >> 21], 1u);
        __syncthreads();
        int b1 = scan_find(hist, 2048, rank, tid, lane, wid, warpS, bc);
        rank -= bc[1];
        __syncthreads();
        // ---- level 2: bits [20:10] ----
        for (int i = tid; i < 2048; i += TPB) hist[i] = 0;
        __syncthreads();
        for (int j = tid; j < NPTS; j += TPB) {
            unsigned k = keys[j];
            if ((int)(k >> 21) == b1) atomicAdd(&hist[(k >> 10) & 0x7FFu], 1u);
        }
        __syncthreads();
        int b2 = scan_find(hist, 2048, rank, tid, lane, wid, warpS, bc);
        rank -= bc[1];
        __syncthreads();
        unsigned pref22 = ((unsigned)b1 << 11) | (unsigned)b2;
        // ---- level 3: bits [9:0] ----
        for (int i = tid; i < 1024; i += TPB) hist[i] = 0;
        __syncthreads();
        for (int j = tid; j < NPTS; j += TPB) {
            unsigned k = keys[j];
            if ((k >> 10) == pref22) atomicAdd(&hist[k & 0x3FFu], 1u);
        }
        __syncthreads();
        int b3 = scan_find(hist, 1024, rank, tid, lane, wid, warpS, bc);
        int eq_needed = rank - bc[1];
        unsigned T = (pref22 << 10) | (unsigned)b3;
        __syncthreads();
        // ---- compaction ----
        if (tid < 2) cnt[tid] = 0;
        eqbuf[tid] = 0xFFFFFFFFu;
        __syncthreads();
        for (int j = tid; j < NPTS; j += TPB) {
            unsigned k = keys[j];
            if (k < T) {
                int pos = atomicAdd(&cnt[0], 1);
                if (pos < 128) cand[pos] = (((unsigned long long)k) << 32) | (unsigned)j;
            } else if (k == T) {
                int pos = atomicAdd(&cnt[1], 1);
                if (pos < 128) eqbuf[pos] = (unsigned)j;
            }
        }
        __syncthreads();
        int c_lt = cnt[0];
        int eq_tot = cnt[1] > 128 ? 128 : cnt[1];
        if (eq_tot > eq_needed) {
            // sort eqbuf ascending (need the eq_needed smallest indices)
            for (int kk = 2; kk <= 128; kk <<= 1)
                for (int jj = kk >> 1; jj > 0; jj >>= 1) {
                    __syncthreads();
                    int ixj = tid ^ jj;
                    if (ixj > tid) {
                        unsigned a = eqbuf[tid], bv = eqbuf[ixj];
                        if ((a > bv) == ((tid & kk) == 0)) { eqbuf[tid] = bv; eqbuf[ixj] = a; }
                    }
                }
            __syncthreads();
        }
        if (tid < eq_needed && c_lt + tid < 128)
            cand[c_lt + tid] = (((unsigned long long)T) << 32) | eqbuf[tid];
        if (tid >= DK) cand[tid] = 0xFFFFFFFFFFFFFFFFull;
        __syncthreads();
        // ---- bitonic sort 128 (key,idx) pairs ----
        for (int kk = 2; kk <= 128; kk <<= 1)
            for (int jj = kk >> 1; jj > 0; jj >>= 1) {
                __syncthreads();
                int ixj = tid ^ jj;
                if (ixj > tid) {
                    unsigned long long a = cand[tid], bv = cand[ixj];
                    if ((a > bv) == ((tid & kk) == 0)) { cand[tid] = bv; cand[ixj] = a; }
                }
            }
        __syncthreads();
        int row = (b << 12) + n;
        if (tid < DK) {
            unsigned long long v = cand[tid];
            unsigned k = (unsigned)(v >> 32);
            unsigned u = ~k;
            unsigned pb = (u & 0x80000000u) ? (u ^ 0x80000000u) : ~u;
            metric_s[tid] = -__uint_as_float(pb);
            g_idx[row * DK + tid] = (int)(unsigned)(v & 0xFFFFFFFFu);
        }
        __syncthreads();
        if (tid < 64) {
            const float* wrow = W_op1 + tid * DK;
            float acc = 0.0f;   // fma chain from 0 == cublas ascending-k accumulate
            #pragma unroll 4
            for (int j2 = 0; j2 < DK; ++j2) acc = fmaf(wrow[j2], metric_s[j2], acc);
            g_mpre[row * 64 + tid] = acc;
            msum += (double)acc;
            msq  += (double)acc * (double)acc;
        }
        __syncthreads();
    }
    if (tid < 64) {
        atomicAdd(&g_msum[tid], msum);
        atomicAdd(&g_msumsq[tid], msq);
    }
}

// ---------------- K2: BN params for m ----------------
__global__ void k2_mbn() {
    int o = threadIdx.x;
    if (o < 64) {
        double S = (double)NROWS;
        double mean = g_msum[o] / S;
        double var = g_msumsq[o] / S - mean * mean;
        g_rm[o] = rsqrtf((float)var + 1e-5f);
        g_meanm[o] = (float)mean;
    }
}

// ---------------- K3: value bins + dilated select + feat moments ----------------
__global__ __launch_bounds__(256) void k3_value(const float* __restrict__ x,
                                                const float* __restrict__ W_op11,
                                                const float* __restrict__ b_op11,
                                                const float* __restrict__ g_op1,
                                                const float* __restrict__ b_op1) {
    int lane = threadIdx.x & 31;
    int gw = blockIdx.x * (blockDim.x >> 5) + (threadIdx.x >> 5);
    int nwarps = gridDim.x * (blockDim.x >> 5);
    float M1l[6] = {0, 0, 0, 0, 0, 0};
    float M2l[21];
    #pragma unroll
    for (int i = 0; i < 21; ++i) M2l[i] = 0.0f;

    for (int p = gw; p < NROWS; p += nwarps) {
        int b = p >> 12, n = p & 4095;
        int val = 0;
        if (lane == 0) {
            // sequential ascending fma chain (cublas-like) for the 64-dot
            float t = 0.0f;
            #pragma unroll 4
            for (int o = 0; o < 64; ++o) {
                float v = g_mpre[p * 64 + o];
                // BN in reference op order: ((x - mean) * r) * gamma + beta (no fma)
                float xn = __fmul_rn(__fsub_rn(v, g_meanm[o]), g_rm[o]);
                float vv = __fadd_rn(__fmul_rn(xn, g_op1[o]), b_op1[o]);
                vv = vv >= 0.0f ? vv : __fmul_rn(0.2f, vv);
                t = fmaf(W_op11[o], vv, t);
            }
            t = __fadd_rn(t, b_op11[0]);
            float mm = __fadd_rn(__fmul_rn(5.0f, 1.0f / (1.0f + expf(t))), 0.5f);
            if      (mm >= 0.5f && mm < 1.5f) val = 1;
            else if (mm >= 1.5f && mm < 2.5f) val = 2;
            else if (mm >= 2.5f && mm < 3.5f) val = 3;
            else if (mm >= 3.5f && mm < 4.5f) val = 4;
            else if (mm >= 4.5f && mm <= 5.5f) val = 5;
        }
        val = __shfl_sync(0xFFFFFFFFu, val, 0);
        if (lane < KNB) {
            int sel = lane * val;
            int id = g_idx[p * DK + sel];
            g_selidx[p * KNB + lane] = id;
            const float* xb = x + b * 3 * NPTS;
            float c0 = xb[n], c1 = xb[NPTS + n], c2 = xb[2 * NPTS + n];
            float n0 = xb[id], n1 = xb[NPTS + id], n2 = xb[2 * NPTS + id];
            float f[6] = {n0 - c0, n1 - c1, n2 - c2, c0, c1, c2};
            #pragma unroll
            for (int i = 0; i < 6; ++i) M1l[i] += f[i];
            #pragma unroll
            for (int i = 0; i < 6; ++i)
                #pragma unroll
                for (int j = 0; j <= i; ++j)
                    M2l[i * (i + 1) / 2 + j] += f[i] * f[j];
        }
    }
    // warp-reduce the moments, lane 0 atomically accumulates to doubles
    #pragma unroll
    for (int i = 0; i < 6; ++i) {
        float v = M1l[i];
        #pragma unroll
        for (int off = 16; off > 0; off >>= 1) v += __shfl_xor_sync(0xFFFFFFFFu, v, off);
        if (lane == 0) atomicAdd(&g_M1[i], (double)v);
    }
    #pragma unroll
    for (int i = 0; i < 21; ++i) {
        float v = M2l[i];
        #pragma unroll
        for (int off = 16; off > 0; off >>= 1) v += __shfl_xor_sync(0xFFFFFFFFu, v, off);
        if (lane == 0) atomicAdd(&g_M2[i], (double)v);
    }
}

// ---------------- K3.5: BN params for h (moment trick) ----------------
__global__ void k35_hbn(const float* __restrict__ W1) {
    int o = threadIdx.x;
    if (o < 64) {
        double S = (double)NROWS * KNB;
        double w[6];
        #pragma unroll
        for (int c = 0; c < 6; ++c) w[c] = (double)W1[o * 6 + c];
        double mean = 0.0;
        #pragma unroll
        for (int c = 0; c < 6; ++c) mean += w[c] * g_M1[c];
        mean /= S;
        double ex2 = 0.0;
        #pragma unroll
        for (int i = 0; i < 6; ++i)
            #pragma unroll
            for (int j = 0; j <= i; ++j)
                ex2 += (i == j ? 1.0 : 2.0) * w[i] * w[j] * g_M2[i * (i + 1) / 2 + j];
        ex2 /= S;
        double var = ex2 - mean * mean;
        g_r1[o] = rsqrtf((float)var + 1e-5f);
        g_mean1[o] = (float)mean;
    }
}

// ---------------- K4: edge conv, BN+lrelu+max over k, write h, SE sums ----------------
__global__ __launch_bounds__(256) void k4_h(const float* __restrict__ x,
                                            const float* __restrict__ W1,
                                            const float* __restrict__ g1,
                                            const float* __restrict__ b1,
                                            float* __restrict__ out) {
    __shared__ float feat_s[KNB][6][32];
    __shared__ float h_s[64][33];
    __shared__ float W1s[64 * 6];
    __shared__ float r1s[64], mean1s[64], g1s[64], b1s[64];
    int tid = threadIdx.x;
    int lane = tid & 31;
    int p0 = blockIdx.x * 32;
    int b = p0 >> 12;
    int nbase = p0 & 4095;
    for (int i = tid; i < 384; i += 256) W1s[i] = W1[i];
    if (tid < 64) {
        r1s[tid] = g_r1[tid]; mean1s[tid] = g_mean1[tid];
        g1s[tid] = g1[tid];   b1s[tid] = b1[tid];
    }
    __syncthreads();
    const float* xb = x + b * 3 * NPTS;
    for (int t = tid; t < 32 * KNB; t += 256) {
        int pt = t / KNB, k = t % KNB;
        int p = p0 + pt, n = nbase + pt;
        int id = g_selidx[p * KNB + k];
        float c0 = xb[n], c1 = xb[NPTS + n], c2 = xb[2 * NPTS + n];
        float n0 = xb[id], n1 = xb[NPTS + id], n2 = xb[2 * NPTS + id];
        feat_s[k][0][pt] = n0 - c0;
        feat_s[k][1][pt] = n1 - c1;
        feat_s[k][2][pt] = n2 - c2;
        feat_s[k][3][pt] = c0;
        feat_s[k][4][pt] = c1;
        feat_s[k][5][pt] = c2;
    }
    __syncthreads();
    for (int e = tid; e < 2048; e += 256) {
        int o = e >> 5, pt = e & 31;
        float r = r1s[o], mn = mean1s[o], gg = g1s[o], bb = b1s[o];
        float w0 = W1s[o * 6 + 0], w1 = W1s[o * 6 + 1], w2 = W1s[o * 6 + 2];
        float w3 = W1s[o * 6 + 3], w4 = W1s[o * 6 + 4], w5 = W1s[o * 6 + 5];
        float best = -1e30f;
        #pragma unroll
        for (int k = 0; k < KNB; ++k) {
            // ascending-k fma chain (cublas-like)
            float hp = __fmul_rn(w0, feat_s[k][0][pt]);
            hp = fmaf(w1, feat_s[k][1][pt], hp);
            hp = fmaf(w2, feat_s[k][2][pt], hp);
            hp = fmaf(w3, feat_s[k][3][pt], hp);
            hp = fmaf(w4, feat_s[k][4][pt], hp);
            hp = fmaf(w5, feat_s[k][5][pt], hp);
            // BN in reference op order
            float xn = __fmul_rn(__fsub_rn(hp, mn), r);
            float hv = __fadd_rn(__fmul_rn(xn, gg), bb);
            hv = hv >= 0.0f ? hv : __fmul_rn(0.2f, hv);
            best = fmaxf(best, hv);
        }
        h_s[o][pt] = best;
    }
    __syncthreads();
    for (int e = tid; e < 2048; e += 256) {
        int o = e >> 5, pos = e & 31;
        float v = h_s[o][pos];
        out[((b << 6) + o) * NPTS + nbase + pos] = v;
        float s = v;
        #pragma unroll
        for (int off = 16; off > 0; off >>= 1) s += __shfl_xor_sync(0xFFFFFFFFu, s, off);
        if (lane == 0) atomicAdd(&g_hsum[(b << 6) + o], (double)s);
    }
}

// ---------------- K5: SE block (tiny, double precision internally) ----------------
__global__ void k5_se(const float* __restrict__ W_sq, const float* __restrict__ g_sq,
                      const float* __restrict__ b_sq, const float* __restrict__ W_ex,
                      const float* __restrict__ g_ex, const float* __restrict__ b_ex) {
    __shared__ double s0[8][64];
    __shared__ double s1[8][8];
    __shared__ double s2t[8][64];
    int t = threadIdx.x; // 64 threads
    for (int i = t; i < 512; i += 64) s0[i >> 6][i & 63] = g_hsum[i] * (1.0 / 4096.0);
    __syncthreads();
    {
        int b = t >> 3, i = t & 7;
        double acc = 0.0;
        for (int o = 0; o < 64; ++o) acc += (double)W_sq[i * 64 + o] * s0[b][o];
        s1[b][i] = acc;
    }
    __syncthreads();
    if (t < 8) {
        double mean = 0.0;
        for (int b = 0; b < 8; ++b) mean += s1[b][t];
        mean *= 0.125;
        double var = 0.0;
        for (int b = 0; b < 8; ++b) { double d = s1[b][t] - mean; var += d * d; }
        var *= 0.125;
        double r = 1.0 / sqrt(var + 1e-5);
        for (int b = 0; b < 8; ++b) {
            double v = (s1[b][t] - mean) * r * (double)g_sq[t] + (double)b_sq[t];
            s1[b][t] = v > 0.0 ? v : 0.0;
        }
    }
    __syncthreads();
    for (int e = t; e < 512; e += 64) {
        int b = e >> 6, o = e & 63;
        double acc = 0.0;
        #pragma unroll
        for (int i = 0; i < 8; ++i) acc += (double)W_ex[o * 8 + i] * s1[b][i];
        s2t[b][o] = acc;
    }
    __syncthreads();
    {
        int o = t;
        double mean = 0.0;
        for (int b = 0; b < 8; ++b) mean += s2t[b][o];
        mean *= 0.125;
        double var = 0.0;
        for (int b = 0; b < 8; ++b) { double d = s2t[b][o] - mean; var += d * d; }
        var *= 0.125;
        double r = 1.0 / sqrt(var + 1e-5);
        for (int b = 0; b < 8; ++b) {
            double v = (s2t[b][o] - mean) * r * (double)g_ex[o] + (double)b_ex[o];
            g_s2[b * 64 + o] = (float)(1.0 / (1.0 + exp(-v)));
        }
    }
}

// ---------------- K6: apply SE gate in place ----------------
__global__ void k6_scale(float* __restrict__ out) {
    int i = blockIdx.x * blockDim.x + threadIdx.x;
    if (i < BATCH * 64 * NPTS) out[i] = __fmul_rn(out[i], g_s2[i >> 12]);
}

// ---------------- launch ----------------
extern "C" void kernel_launch(void* const* d_in, const int* in_sizes, int n_in,
                              void* d_out, int out_size) {
    const float* x      = (const float*)d_in[0];
    const float* W_op1  = (const float*)d_in[1];
    const float* g_op1  = (const float*)d_in[2];
    const float* b_op1  = (const float*)d_in[3];
    const float* W_op11 = (const float*)d_in[4];
    const float* b_op11 = (const float*)d_in[5];
    const float* W1     = (const float*)d_in[6];
    const float* g1     = (const float*)d_in[7];
    const float* b1     = (const float*)d_in[8];
    const float* W_sq   = (const float*)d_in[9];
    const float* g_sq   = (const float*)d_in[10];
    const float* b_sq   = (const float*)d_in[11];
    const float* W_ex   = (const float*)d_in[12];
    const float* g_ex   = (const float*)d_in[13];
    const float* b_ex   = (const float*)d_in[14];
    float* out = (float*)d_out;

    const int smem_k1 = 92192;
    cudaFuncSetAttribute(k1_topk, cudaFuncAttributeMaxDynamicSharedMemorySize, smem_k1);

    k0_zero<<<1, 512>>>();
    k1_topk<<<dim3(64, 8), TPB, smem_k1>>>(x, W_op1);
    k2_mbn<<<1, 64>>>();
    k3_value<<<128, 256>>>(x, W_op11, b_op11, g_op1, b_op1);
    k35_hbn<<<1, 64>>>(W1);
    k4_h<<<1024, 256>>>(x, W1, g1, b1, out);
    k5_se<<<1, 64>>>(W_sq, g_sq, b_sq, W_ex, g_ex, b_ex);
    k6_scale<<<(BATCH * 64 * NPTS + 255) / 256, 256>>>(out);
}

// round 3
// speedup vs baseline: 1.7357x; 1.7357x over previous
#include <cuda_runtime.h>
#include <cuda_bf16.h>
#include <math.h>

#define NPTS 4096
#define BATCH 8
#define NROWS (BATCH*NPTS)     // 32768
#define DK 100
#define KNB 20
#define TPB1 256

// ---------------- device scratch (no runtime allocation allowed) ----------------
__device__ double g_msum[64];
__device__ double g_msumsq[64];
__device__ double g_M1[6];
__device__ double g_M2[21];
__device__ double g_hsum[512];          // [b][o]
__device__ float  g_mpre[NROWS * 64];   // [row][o]
__device__ int    g_idx[NROWS * DK];    // [row][100]
__device__ int    g_selidx[NROWS * KNB];// [row][20]
__device__ float  g_rm[64], g_meanm[64];   // m-BN rsqrt / mean
__device__ float  g_r1[64], g_mean1[64];   // h-BN rsqrt / mean
__device__ float  g_s2[512];            // SE gate [b][o]

// ---------------- K0: zero accumulators ----------------
__global__ void k0_zero() {
    int t = threadIdx.x;
    if (t < 64) { g_msum[t] = 0.0; g_msumsq[t] = 0.0; }
    if (t < 6)  g_M1[t] = 0.0;
    if (t < 21) g_M2[t] = 0.0;
    if (t < 512) g_hsum[t] = 0.0;
}

// ---------------- scan_find: block-wide histogram rank search (256 threads) ----------------
__device__ __forceinline__ int scan_find(unsigned* hist, int H, int rankv,
                                         int tid, int lane, int wid,
                                         unsigned* warpS, int* bc) {
    int chunk = H >> 8;          // H / 256
    int base = tid * chunk;
    unsigned local = 0;
    for (int i = 0; i < chunk; ++i) local += hist[base + i];
    unsigned v = local;
    #pragma unroll
    for (int off = 1; off < 32; off <<= 1) {
        unsigned t2 = __shfl_up_sync(0xFFFFFFFFu, v, off);
        if (lane >= off) v += t2;
    }
    if (lane == 31) warpS[wid] = v;
    __syncthreads();
    if (tid == 0) {
        unsigned s = 0;
        for (int w = 0; w < 8; ++w) { unsigned t2 = warpS[w]; warpS[w] = s; s += t2; }
    }
    __syncthreads();
    unsigned incl = v + warpS[wid];
    unsigned excl = incl - local;
    if (excl < (unsigned)rankv && (unsigned)rankv <= incl) {
        unsigned c = excl;
        for (int i = 0; i < chunk; ++i) {
            unsigned h = hist[base + i];
            if (c < (unsigned)rankv && (unsigned)rankv <= c + h) { bc[0] = base + i; bc[1] = (int)c; break; }
            c += h;
        }
    }
    __syncthreads();
    return bc[0];
}

// ---------------- warp-register bitonic sort of 128 u64, 4 per lane ----------------
__device__ __forceinline__ void warp_sort128(unsigned long long r[4], int lane) {
    #pragma unroll
    for (int kk = 2; kk <= 128; kk <<= 1) {
        #pragma unroll
        for (int jj = kk >> 1; jj > 0; jj >>= 1) {
            if (jj >= 32) {
                int em = jj >> 5;
                #pragma unroll
                for (int e = 0; e < 4; ++e) {
                    if (!(e & em)) {
                        bool up = ((((unsigned)e << 5) & (unsigned)kk) == 0u);
                        unsigned long long a = r[e], bv = r[e ^ em];
                        unsigned long long mn = a < bv ? a : bv;
                        unsigned long long mx = a < bv ? bv : a;
                        r[e] = up ? mn : mx;
                        r[e ^ em] = up ? mx : mn;
                    }
                }
            } else {
                #pragma unroll
                for (int e = 0; e < 4; ++e) {
                    unsigned g = ((unsigned)e << 5) | (unsigned)lane;
                    bool up = ((g & (unsigned)kk) == 0u);
                    unsigned long long other = __shfl_xor_sync(0xFFFFFFFFu, r[e], jj);
                    bool lower = ((lane & jj) == 0);
                    unsigned long long mn = r[e] < other ? r[e] : other;
                    unsigned long long mx = r[e] < other ? other : r[e];
                    r[e] = (lower == up) ? mn : mx;
                }
            }
        }
    }
}

// ---------------- K1: per-row top-100 select + sort + W_op1 matmul ----------------
__global__ __launch_bounds__(TPB1, 3) void k1_topk(const float* __restrict__ x,
                                                   const float* __restrict__ W_op1) {
    extern __shared__ char smem_raw[];
    float*    xs     = (float*)smem_raw;                                  // 49152
    unsigned* hist   = (unsigned*)(smem_raw + 49152);                     // 8192
    unsigned long long* cand = (unsigned long long*)(smem_raw + 57344);   // 1024
    float*    metric_s = (float*)(smem_raw + 58368);                      // 512
    unsigned* warpS  = (unsigned*)(smem_raw + 58880);                     // 32
    int*      bc     = (int*)(smem_raw + 58912);                          // 8
    int*      cnt    = (int*)(smem_raw + 58920);                          // 4

    int tid = threadIdx.x, lane = tid & 31, wid = tid >> 5;
    int b = blockIdx.y;
    const float* xb = x + b * 3 * NPTS;
    for (int i = tid; i < 3 * NPTS; i += TPB1) xs[i] = xb[i];
    __syncthreads();

    double msum = 0.0, msq = 0.0;

    for (int r = 0; r < 32; ++r) {
        int n = blockIdx.x * 32 + r;
        float x0n = xs[n], x1n = xs[NPTS + n], x2n = xs[2 * NPTS + n];
        float xxn = __fadd_rn(__fadd_rn(__fmul_rn(x0n, x0n), __fmul_rn(x1n, x1n)), __fmul_rn(x2n, x2n));

        // ---- compute keys into registers (numerics identical to R2) ----
        unsigned kreg[16];
        #pragma unroll
        for (int it = 0; it < 16; ++it) {
            int j = it * TPB1 + tid;
            float a0 = xs[j], a1 = xs[NPTS + j], a2 = xs[2 * NPTS + j];
            float inner = __fmul_rn(x0n, a0);
            inner = fmaf(x1n, a1, inner);
            inner = fmaf(x2n, a2, inner);
            float xxj = __fadd_rn(__fadd_rn(__fmul_rn(a0, a0), __fmul_rn(a1, a1)), __fmul_rn(a2, a2));
            float p = __fsub_rn(__fsub_rn(__fmul_rn(2.0f, inner), xxn), xxj);
            unsigned bits = __float_as_uint(p);
            unsigned u = (bits & 0x80000000u) ? ~bits : (bits | 0x80000000u);
            kreg[it] = ~u;   // ascending key == descending p
        }

        int rank = DK;
        // ---- level 1: bits [31:21] ----
        for (int i = tid; i < 2048; i += TPB1) hist[i] = 0;
        __syncthreads();
        #pragma unroll
        for (int it = 0; it < 16; ++it) atomicAdd(&hist[kreg[it] >> 21], 1u);
        __syncthreads();
        int b1 = scan_find(hist, 2048, rank, tid, lane, wid, warpS, bc);
        rank -= bc[1];
        __syncthreads();
        // ---- level 2: bits [20:10] ----
        for (int i = tid; i < 2048; i += TPB1) hist[i] = 0;
        __syncthreads();
        #pragma unroll
        for (int it = 0; it < 16; ++it) {
            unsigned k = kreg[it];
            if ((int)(k >> 21) == b1) atomicAdd(&hist[(k >> 10) & 0x7FFu], 1u);
        }
        __syncthreads();
        int b2 = scan_find(hist, 2048, rank, tid, lane, wid, warpS, bc);
        rank -= bc[1];
        __syncthreads();
        unsigned pref22 = ((unsigned)b1 << 11) | (unsigned)b2;
        // ---- level 3: bits [9:0] ----
        for (int i = tid; i < 1024; i += TPB1) hist[i] = 0;
        __syncthreads();
        #pragma unroll
        for (int it = 0; it < 16; ++it) {
            unsigned k = kreg[it];
            if ((k >> 10) == pref22) atomicAdd(&hist[k & 0x3FFu], 1u);
        }
        __syncthreads();
        int b3 = scan_find(hist, 1024, rank, tid, lane, wid, warpS, bc);
        unsigned T = (pref22 << 10) | (unsigned)b3;

        // ---- compaction: all keys <= T (ties auto-ordered by idx in u64 sort) ----
        if (tid == 0) cnt[0] = 0;
        if (tid < 128) cand[tid] = 0xFFFFFFFFFFFFFFFFull;
        __syncthreads();
        #pragma unroll
        for (int it = 0; it < 16; ++it) {
            bool pr = kreg[it] <= T;
            unsigned m = __ballot_sync(0xFFFFFFFFu, pr);
            if (m) {
                int leader = __ffs(m) - 1;
                int base = 0;
                if (lane == leader) base = atomicAdd(cnt, __popc(m));
                base = __shfl_sync(0xFFFFFFFFu, base, leader);
                if (pr) {
                    int pos = base + __popc(m & ((1u << lane) - 1u));
                    if (pos < 128)
                        cand[pos] = (((unsigned long long)kreg[it]) << 32) | (unsigned)(it * TPB1 + tid);
                }
            }
        }
        __syncthreads();

        // ---- warp 0: in-register bitonic sort of 128 candidates ----
        int row = (b << 12) + n;
        if (wid == 0) {
            unsigned long long rr[4];
            #pragma unroll
            for (int e = 0; e < 4; ++e) rr[e] = cand[(e << 5) | lane];
            warp_sort128(rr, lane);
            #pragma unroll
            for (int e = 0; e < 4; ++e) {
                int g = (e << 5) | lane;
                if (g < DK) {
                    unsigned k = (unsigned)(rr[e] >> 32);
                    unsigned u = ~k;
                    unsigned pb = (u & 0x80000000u) ? (u ^ 0x80000000u) : ~u;
                    metric_s[g] = -__uint_as_float(pb);
                    g_idx[row * DK + g] = (int)(unsigned)(rr[e] & 0xFFFFFFFFull);
                }
            }
        }
        __syncthreads();

        // ---- matmul m_pre = W_op1 . metric (ascending-k fma chain, as R2) ----
        if (tid < 64) {
            const float* wrow = W_op1 + tid * DK;
            float acc = 0.0f;
            #pragma unroll 4
            for (int j2 = 0; j2 < DK; ++j2) acc = fmaf(wrow[j2], metric_s[j2], acc);
            g_mpre[row * 64 + tid] = acc;
            msum += (double)acc;
            msq  += (double)acc * (double)acc;
        }
        __syncthreads();
    }
    if (tid < 64) {
        atomicAdd(&g_msum[tid], msum);
        atomicAdd(&g_msumsq[tid], msq);
    }
}

// ---------------- K2: BN params for m ----------------
__global__ void k2_mbn() {
    int o = threadIdx.x;
    if (o < 64) {
        double S = (double)NROWS;
        double mean = g_msum[o] / S;
        double var = g_msumsq[o] / S - mean * mean;
        g_rm[o] = rsqrtf((float)var + 1e-5f);
        g_meanm[o] = (float)mean;
    }
}

// ---------------- K3: value bins + dilated select + feat moments (thread per point) ----------------
__global__ __launch_bounds__(256) void k3_value(const float* __restrict__ x,
                                                const float* __restrict__ W_op11,
                                                const float* __restrict__ b_op11,
                                                const float* __restrict__ g_op1,
                                                const float* __restrict__ b_op1) {
    __shared__ float s_mean[64], s_r[64], s_gm[64], s_bt[64], s_w[64];
    int tid = threadIdx.x;
    int lane = tid & 31;
    if (tid < 64) {
        s_mean[tid] = g_meanm[tid]; s_r[tid] = g_rm[tid];
        s_gm[tid] = g_op1[tid];     s_bt[tid] = b_op1[tid];
        s_w[tid] = W_op11[tid];
    }
    __syncthreads();
    int p = blockIdx.x * 256 + tid;     // grid is exactly NROWS/256 blocks
    int b = p >> 12, n = p & 4095;
    const float* mp = g_mpre + p * 64;
    // sequential ascending fma chain (identical op order to R2)
    float t = 0.0f;
    #pragma unroll 8
    for (int o = 0; o < 64; ++o) {
        float v = mp[o];
        float xn = __fmul_rn(__fsub_rn(v, s_mean[o]), s_r[o]);
        float vv = __fadd_rn(__fmul_rn(xn, s_gm[o]), s_bt[o]);
        vv = vv >= 0.0f ? vv : __fmul_rn(0.2f, vv);
        t = fmaf(s_w[o], vv, t);
    }
    t = __fadd_rn(t, b_op11[0]);
    float mm = __fadd_rn(__fmul_rn(5.0f, 1.0f / (1.0f + expf(t))), 0.5f);
    int val = 0;
    if      (mm >= 0.5f && mm < 1.5f) val = 1;
    else if (mm >= 1.5f && mm < 2.5f) val = 2;
    else if (mm >= 2.5f && mm < 3.5f) val = 3;
    else if (mm >= 3.5f && mm < 4.5f) val = 4;
    else if (mm >= 4.5f && mm <= 5.5f) val = 5;

    const float* xb = x + b * 3 * NPTS;
    float c0 = xb[n], c1 = xb[NPTS + n], c2 = xb[2 * NPTS + n];
    const int* ip = g_idx + p * DK;
    int* sp = g_selidx + p * KNB;
    float M1l[6] = {0, 0, 0, 0, 0, 0};
    float M2l[21];
    #pragma unroll
    for (int i = 0; i < 21; ++i) M2l[i] = 0.0f;
    #pragma unroll 4
    for (int k = 0; k < KNB; ++k) {
        int id = ip[k * val];
        sp[k] = id;
        float n0 = xb[id], n1 = xb[NPTS + id], n2 = xb[2 * NPTS + id];
        float f[6] = {n0 - c0, n1 - c1, n2 - c2, c0, c1, c2};
        #pragma unroll
        for (int i = 0; i < 6; ++i) M1l[i] += f[i];
        #pragma unroll
        for (int i = 0; i < 6; ++i)
            #pragma unroll
            for (int j = 0; j <= i; ++j)
                M2l[i * (i + 1) / 2 + j] += f[i] * f[j];
    }
    // warp-reduce the moments, lane 0 atomically accumulates to doubles
    #pragma unroll
    for (int i = 0; i < 6; ++i) {
        float v = M1l[i];
        #pragma unroll
        for (int off = 16; off > 0; off >>= 1) v += __shfl_xor_sync(0xFFFFFFFFu, v, off);
        if (lane == 0) atomicAdd(&g_M1[i], (double)v);
    }
    #pragma unroll
    for (int i = 0; i < 21; ++i) {
        float v = M2l[i];
        #pragma unroll
        for (int off = 16; off > 0; off >>= 1) v += __shfl_xor_sync(0xFFFFFFFFu, v, off);
        if (lane == 0) atomicAdd(&g_M2[i], (double)v);
    }
}

// ---------------- K3.5: BN params for h (moment trick) ----------------
__global__ void k35_hbn(const float* __restrict__ W1) {
    int o = threadIdx.x;
    if (o < 64) {
        double S = (double)NROWS * KNB;
        double w[6];
        #pragma unroll
        for (int c = 0; c < 6; ++c) w[c] = (double)W1[o * 6 + c];
        double mean = 0.0;
        #pragma unroll
        for (int c = 0; c < 6; ++c) mean += w[c] * g_M1[c];
        mean /= S;
        double ex2 = 0.0;
        #pragma unroll
        for (int i = 0; i < 6; ++i)
            #pragma unroll
            for (int j = 0; j <= i; ++j)
                ex2 += (i == j ? 1.0 : 2.0) * w[i] * w[j] * g_M2[i * (i + 1) / 2 + j];
        ex2 /= S;
        double var = ex2 - mean * mean;
        g_r1[o] = rsqrtf((float)var + 1e-5f);
        g_mean1[o] = (float)mean;
    }
}

// ---------------- K4: edge conv, BN+lrelu+max over k, write h, SE sums ----------------
__global__ __launch_bounds__(256) void k4_h(const float* __restrict__ x,
                                            const float* __restrict__ W1,
                                            const float* __restrict__ g1,
                                            const float* __restrict__ b1,
                                            float* __restrict__ out) {
    __shared__ float feat_s[KNB][6][32];
    __shared__ float h_s[64][33];
    __shared__ float W1s[64 * 6];
    __shared__ float r1s[64], mean1s[64], g1s[64], b1s[64];
    int tid = threadIdx.x;
    int lane = tid & 31;
    int p0 = blockIdx.x * 32;
    int b = p0 >> 12;
    int nbase = p0 & 4095;
    for (int i = tid; i < 384; i += 256) W1s[i] = W1[i];
    if (tid < 64) {
        r1s[tid] = g_r1[tid]; mean1s[tid] = g_mean1[tid];
        g1s[tid] = g1[tid];   b1s[tid] = b1[tid];
    }
    __syncthreads();
    const float* xb = x + b * 3 * NPTS;
    for (int t = tid; t < 32 * KNB; t += 256) {
        int pt = t / KNB, k = t % KNB;
        int p = p0 + pt, n = nbase + pt;
        int id = g_selidx[p * KNB + k];
        float c0 = xb[n], c1 = xb[NPTS + n], c2 = xb[2 * NPTS + n];
        float n0 = xb[id], n1 = xb[NPTS + id], n2 = xb[2 * NPTS + id];
        feat_s[k][0][pt] = n0 - c0;
        feat_s[k][1][pt] = n1 - c1;
        feat_s[k][2][pt] = n2 - c2;
        feat_s[k][3][pt] = c0;
        feat_s[k][4][pt] = c1;
        feat_s[k][5][pt] = c2;
    }
    __syncthreads();
    for (int e = tid; e < 2048; e += 256) {
        int o = e >> 5, pt = e & 31;
        float r = r1s[o], mn = mean1s[o], gg = g1s[o], bb = b1s[o];
        float w0 = W1s[o * 6 + 0], w1 = W1s[o * 6 + 1], w2 = W1s[o * 6 + 2];
        float w3 = W1s[o * 6 + 3], w4 = W1s[o * 6 + 4], w5 = W1s[o * 6 + 5];
        float best = -1e30f;
        #pragma unroll
        for (int k = 0; k < KNB; ++k) {
            float hp = __fmul_rn(w0, feat_s[k][0][pt]);
            hp = fmaf(w1, feat_s[k][1][pt], hp);
            hp = fmaf(w2, feat_s[k][2][pt], hp);
            hp = fmaf(w3, feat_s[k][3][pt], hp);
            hp = fmaf(w4, feat_s[k][4][pt], hp);
            hp = fmaf(w5, feat_s[k][5][pt], hp);
            float xn = __fmul_rn(__fsub_rn(hp, mn), r);
            float hv = __fadd_rn(__fmul_rn(xn, gg), bb);
            hv = hv >= 0.0f ? hv : __fmul_rn(0.2f, hv);
            best = fmaxf(best, hv);
        }
        h_s[o][pt] = best;
    }
    __syncthreads();
    for (int e = tid; e < 2048; e += 256) {
        int o = e >> 5, pos = e & 31;
        float v = h_s[o][pos];
        out[((b << 6) + o) * NPTS + nbase + pos] = v;
        float s = v;
        #pragma unroll
        for (int off = 16; off > 0; off >>= 1) s += __shfl_xor_sync(0xFFFFFFFFu, s, off);
        if (lane == 0) atomicAdd(&g_hsum[(b << 6) + o], (double)s);
    }
}

// ---------------- K5: SE block (tiny, double precision internally) ----------------
__global__ void k5_se(const float* __restrict__ W_sq, const float* __restrict__ g_sq,
                      const float* __restrict__ b_sq, const float* __restrict__ W_ex,
                      const float* __restrict__ g_ex, const float* __restrict__ b_ex) {
    __shared__ double s0[8][64];
    __shared__ double s1[8][8];
    __shared__ double s2t[8][64];
    int t = threadIdx.x; // 64 threads
    for (int i = t; i < 512; i += 64) s0[i >> 6][i & 63] = g_hsum[i] * (1.0 / 4096.0);
    __syncthreads();
    {
        int b = t >> 3, i = t & 7;
        double acc = 0.0;
        for (int o = 0; o < 64; ++o) acc += (double)W_sq[i * 64 + o] * s0[b][o];
        s1[b][i] = acc;
    }
    __syncthreads();
    if (t < 8) {
        double mean = 0.0;
        for (int b = 0; b < 8; ++b) mean += s1[b][t];
        mean *= 0.125;
        double var = 0.0;
        for (int b = 0; b < 8; ++b) { double d = s1[b][t] - mean; var += d * d; }
        var *= 0.125;
        double r = 1.0 / sqrt(var + 1e-5);
        for (int b = 0; b < 8; ++b) {
            double v = (s1[b][t] - mean) * r * (double)g_sq[t] + (double)b_sq[t];
            s1[b][t] = v > 0.0 ? v : 0.0;
        }
    }
    __syncthreads();
    for (int e = t; e < 512; e += 64) {
        int b = e >> 6, o = e & 63;
        double acc = 0.0;
        #pragma unroll
        for (int i = 0; i < 8; ++i) acc += (double)W_ex[o * 8 + i] * s1[b][i];
        s2t[b][o] = acc;
    }
    __syncthreads();
    {
        int o = t;
        double mean = 0.0;
        for (int b = 0; b < 8; ++b) mean += s2t[b][o];
        mean *= 0.125;
        double var = 0.0;
        for (int b = 0; b < 8; ++b) { double d = s2t[b][o] - mean; var += d * d; }
        var *= 0.125;
        double r = 1.0 / sqrt(var + 1e-5);
        for (int b = 0; b < 8; ++b) {
            double v = (s2t[b][o] - mean) * r * (double)g_ex[o] + (double)b_ex[o];
            g_s2[b * 64 + o] = (float)(1.0 / (1.0 + exp(-v)));
        }
    }
}

// ---------------- K6: apply SE gate in place ----------------
__global__ void k6_scale(float* __restrict__ out) {
    int i = blockIdx.x * blockDim.x + threadIdx.x;
    if (i < BATCH * 64 * NPTS) out[i] = __fmul_rn(out[i], g_s2[i >> 12]);
}

// ---------------- launch ----------------
extern "C" void kernel_launch(void* const* d_in, const int* in_sizes, int n_in,
                              void* d_out, int out_size) {
    const float* x      = (const float*)d_in[0];
    const float* W_op1  = (const float*)d_in[1];
    const float* g_op1  = (const float*)d_in[2];
    const float* b_op1  = (const float*)d_in[3];
    const float* W_op11 = (const float*)d_in[4];
    const float* b_op11 = (const float*)d_in[5];
    const float* W1     = (const float*)d_in[6];
    const float* g1     = (const float*)d_in[7];
    const float* b1     = (const float*)d_in[8];
    const float* W_sq   = (const float*)d_in[9];
    const float* g_sq   = (const float*)d_in[10];
    const float* b_sq   = (const float*)d_in[11];
    const float* W_ex   = (const float*)d_in[12];
    const float* g_ex   = (const float*)d_in[13];
    const float* b_ex   = (const float*)d_in[14];
    float* out = (float*)d_out;

    const int smem_k1 = 58944;
    cudaFuncSetAttribute(k1_topk, cudaFuncAttributeMaxDynamicSharedMemorySize, smem_k1);

    k0_zero<<<1, 512>>>();
    k1_topk<<<dim3(128, 8), TPB1, smem_k1>>>(x, W_op1);
    k2_mbn<<<1, 64>>>();
    k3_value<<<NROWS / 256, 256>>>(x, W_op11, b_op11, g_op1, b_op1);
    k35_hbn<<<1, 64>>>(W1);
    k4_h<<<1024, 256>>>(x, W1, g1, b1, out);
    k5_se<<<1, 64>>>(W_sq, g_sq, b_sq, W_ex, g_ex, b_ex);
    k6_scale<<<(BATCH * 64 * NPTS + 255) / 256, 256>>>(out);
}